// round 12
// baseline (speedup 1.0000x reference)
#include <cuda_runtime.h>
#include <cuda_bf16.h>
#include <cstdint>

#define DINL __device__ __forceinline__

namespace {
constexpr int   kBatch    = 524288;
constexpr int   kRowsCTA  = 64;                      // 4 warps x 16 rows
constexpr int   kNumTiles = kBatch / kRowsCTA;       // 8192
constexpr int   kThreads  = 128;
constexpr float kDT = 0.01f;

// SMEM offsets in uint32 units
constexpr int OFF_W2   = 0;      // W2  B-frags [8 ks][8 np][32 lane] uint4 -> 8192 u32
constexpr int OFF_W2T  = 8192;   // W2^T B-frags, same layout               -> 8192 u32
constexpr int OFF_W1   = 16384;  // W1 k8 B-frags [8 np][32 lane] uint2     -> 512 u32
constexpr int OFF_W1T  = 16896;  // W1^T B-frags [8 ks][32 lane] uint2      -> 512 u32
constexpr int OFF_B1   = 17408;  // f32[128]
constexpr int OFF_B2   = 17536;  // f32[128]
constexpr int OFF_W3B  = 17664;  // bf16x2[64]  (+W3 pairs)
constexpr int OFF_NW3B = 17728;  // bf16x2[64]  (-W3 pairs)
constexpr int kSmemU32 = 17792;  // 71168 bytes -> 3 CTAs/SM = 213.5 KB
}

DINL uint32_t pack_bf2(float lo, float hi) {
    __nv_bfloat162 t = __floats2bfloat162_rn(lo, hi);
    return *reinterpret_cast<uint32_t*>(&t);
}
// bf16x2 vector ops (HFMA2/MUFU pipes)
DINL uint32_t tanh2(uint32_t x) { uint32_t r; asm("tanh.approx.bf16x2 %0, %1;" : "=r"(r) : "r"(x)); return r; }
DINL uint32_t mul2(uint32_t a, uint32_t b) { uint32_t r; asm("mul.rn.bf16x2 %0, %1, %2;" : "=r"(r) : "r"(a), "r"(b)); return r; }
DINL uint32_t fma2(uint32_t a, uint32_t b, uint32_t c) { uint32_t r; asm("fma.rn.bf16x2 %0, %1, %2, %3;" : "=r"(r) : "r"(a), "r"(b), "r"(c)); return r; }
DINL uint32_t neg2(uint32_t a) { uint32_t r; asm("neg.bf16x2 %0, %1;" : "=r"(r) : "r"(a)); return r; }

// D = A(16x16 bf16) x B(16x8 bf16) + D, fp32 accum
DINL void mma16816(float* c, uint32_t a0, uint32_t a1, uint32_t a2, uint32_t a3,
                   uint32_t b0, uint32_t b1) {
    asm volatile(
        "mma.sync.aligned.m16n8k16.row.col.f32.bf16.bf16.f32 "
        "{%0,%1,%2,%3}, {%4,%5,%6,%7}, {%8,%9}, {%0,%1,%2,%3};"
        : "+f"(c[0]), "+f"(c[1]), "+f"(c[2]), "+f"(c[3])
        : "r"(a0), "r"(a1), "r"(a2), "r"(a3), "r"(b0), "r"(b1));
}
// D = A(16x8 bf16) x B(8x8 bf16) + D (layer 1: true K = 8)
DINL void mma16808(float* c, uint32_t a0, uint32_t a1, uint32_t b0) {
    asm volatile(
        "mma.sync.aligned.m16n8k8.row.col.f32.bf16.bf16.f32 "
        "{%0,%1,%2,%3}, {%4,%5}, {%6}, {%0,%1,%2,%3};"
        : "+f"(c[0]), "+f"(c[1]), "+f"(c[2]), "+f"(c[3])
        : "r"(a0), "r"(a1), "r"(b0));
}

// -----------------------------------------------------------------------------
// grad_eval: 16 rows/warp. GEMMs chunked into two halves of 8 nt (acc[32]
// live instead of acc[64]) so the whole kernel fits the 170-reg cap of
// 3 CTAs/SM — the measured bottleneck is cross-pipe overlap (tensor busy ==
// LDS busy == ~247us; only 7.4 warps/SM means they serialize).
// Layer-3 elementwise writes dpre1 INTO hf in place: hf[nt] is dead exactly
// when dpre1[nt] is produced, while gf must survive both halves as A operand.
// -----------------------------------------------------------------------------
DINL void grad_eval(const uint4* __restrict__ w2f,  const uint4* __restrict__ w2tf,
                    const uint2* __restrict__ w1f,  const uint2* __restrict__ w1tf,
                    const float2* __restrict__ b1v, const float2* __restrict__ b2v,
                    const uint32_t* __restrict__ w3b, const uint32_t* __restrict__ nw3b,
                    int lane, const float s[4], float d[4]) {
    const int tg = lane & 3;
    const uint32_t az0 = pack_bf2(s[0], s[1]);   // row g,   k=2tg..2tg+1
    const uint32_t az1 = pack_bf2(s[2], s[3]);   // row g+8
    uint32_t hf[32];   // h1 A-frags (K=128); overwritten by dpre1 in layer 3
    uint32_t gf[32];   // dpre2 A-frags

    // ---- layer 1 (k8): h1 = tanh(z @ W1 + b1), two halves of 4 np ----
#pragma unroll
    for (int half = 0; half < 2; half++) {
        float acc[32];
#pragma unroll
        for (int i = 0; i < 32; i++) acc[i] = 0.f;
#pragma unroll
        for (int j = 0; j < 4; j++) {
            const int np = 4 * half + j;
            const uint2 b = w1f[np * 32 + lane];
            mma16808(acc + 8 * j,     az0, az1, b.x);
            mma16808(acc + 8 * j + 4, az0, az1, b.y);
        }
#pragma unroll
        for (int j = 0; j < 8; j++) {
            const int nt = 8 * half + j;
            const float2 bb = b1v[nt * 4 + tg];
            hf[2*nt]   = tanh2(pack_bf2(acc[4*j]   + bb.x, acc[4*j+1] + bb.y));
            hf[2*nt+1] = tanh2(pack_bf2(acc[4*j+2] + bb.x, acc[4*j+3] + bb.y));
        }
    }

    // ---- layer 2: dpre2 = w3*(1 - tanh(h1 @ W2 + b2)^2), two halves of 4 np ----
#pragma unroll
    for (int half = 0; half < 2; half++) {
        float acc[32];
#pragma unroll
        for (int i = 0; i < 32; i++) acc[i] = 0.f;
#pragma unroll
        for (int ks = 0; ks < 8; ks++) {
            const uint32_t a0 = hf[4*ks], a1 = hf[4*ks+1], a2 = hf[4*ks+2], a3 = hf[4*ks+3];
#pragma unroll
            for (int j = 0; j < 4; j++) {
                const uint4 b = w2f[(ks * 8 + 4 * half + j) * 32 + lane];
                mma16816(acc + 8 * j,     a0, a1, a2, a3, b.x, b.y);
                mma16816(acc + 8 * j + 4, a0, a1, a2, a3, b.z, b.w);
            }
        }
#pragma unroll
        for (int j = 0; j < 8; j++) {
            const int nt = 8 * half + j;
            const float2 bb = b2v[nt * 4 + tg];
            const uint32_t w3p  = w3b[nt * 4 + tg];
            const uint32_t nw3p = nw3b[nt * 4 + tg];
            uint32_t t0 = tanh2(pack_bf2(acc[4*j]   + bb.x, acc[4*j+1] + bb.y));
            uint32_t t1 = tanh2(pack_bf2(acc[4*j+2] + bb.x, acc[4*j+3] + bb.y));
            gf[2*nt]   = fma2(nw3p, mul2(t0, t0), w3p);
            gf[2*nt+1] = fma2(nw3p, mul2(t1, t1), w3p);
        }
    }

    // ---- layer 3: dpre1 = (dpre2 @ W2^T) * (1 - h1^2), halves; writes hf ----
#pragma unroll
    for (int half = 0; half < 2; half++) {
        float acc[32];
#pragma unroll
        for (int i = 0; i < 32; i++) acc[i] = 0.f;
#pragma unroll
        for (int ks = 0; ks < 8; ks++) {
            const uint32_t a0 = gf[4*ks], a1 = gf[4*ks+1], a2 = gf[4*ks+2], a3 = gf[4*ks+3];
#pragma unroll
            for (int j = 0; j < 4; j++) {
                const uint4 b = w2tf[(ks * 8 + 4 * half + j) * 32 + lane];
                mma16816(acc + 8 * j,     a0, a1, a2, a3, b.x, b.y);
                mma16816(acc + 8 * j + 4, a0, a1, a2, a3, b.z, b.w);
            }
        }
#pragma unroll
        for (int j = 0; j < 8; j++) {
            const int nt = 8 * half + j;
            uint32_t v0 = pack_bf2(acc[4*j],   acc[4*j+1]);
            uint32_t v1 = pack_bf2(acc[4*j+2], acc[4*j+3]);
            const uint32_t h0 = hf[2*nt], h1 = hf[2*nt+1];
            hf[2*nt]   = fma2(neg2(v0), mul2(h0, h0), v0);
            hf[2*nt+1] = fma2(neg2(v1), mul2(h1, h1), v1);
        }
    }

    // ---- layer 4: dz = dpre1 @ W1^T ----
    d[0] = d[1] = d[2] = d[3] = 0.f;
#pragma unroll
    for (int ks = 0; ks < 8; ks++) {
        const uint2 bw = w1tf[ks * 32 + lane];
        mma16816(d, hf[4*ks], hf[4*ks+1], hf[4*ks+2], hf[4*ks+3], bw.x, bw.y);
    }
}

// -----------------------------------------------------------------------------
__global__ void __launch_bounds__(kThreads, 3)
symp_kernel(const float* __restrict__ z,  const float* __restrict__ W1,
            const float* __restrict__ b1, const float* __restrict__ W2,
            const float* __restrict__ b2, const float* __restrict__ W3,
            const float* __restrict__ b3, float* __restrict__ out) {
    extern __shared__ uint32_t sm[];
    const int tid = threadIdx.x;
    const int wid = tid >> 5, lane = tid & 31;

    // ---- build weight B-fragments in SMEM (once per persistent CTA) ----
    for (int idx = tid; idx < 8 * 8 * 32; idx += kThreads) {
        int ks = idx >> 8, np = (idx >> 5) & 7, ln = idx & 31;
        int n0 = (2 * np) * 8 + (ln >> 2);
        int n1 = n0 + 8;
        int kb = ks * 16 + (ln & 3) * 2;
        ((uint4*)(sm + OFF_W2))[idx] = make_uint4(
            pack_bf2(W2[kb * 128 + n0],       W2[(kb + 1) * 128 + n0]),
            pack_bf2(W2[(kb + 8) * 128 + n0], W2[(kb + 9) * 128 + n0]),
            pack_bf2(W2[kb * 128 + n1],       W2[(kb + 1) * 128 + n1]),
            pack_bf2(W2[(kb + 8) * 128 + n1], W2[(kb + 9) * 128 + n1]));
        ((uint4*)(sm + OFF_W2T))[idx] = make_uint4(
            pack_bf2(W2[n0 * 128 + kb],     W2[n0 * 128 + kb + 1]),
            pack_bf2(W2[n0 * 128 + kb + 8], W2[n0 * 128 + kb + 9]),
            pack_bf2(W2[n1 * 128 + kb],     W2[n1 * 128 + kb + 1]),
            pack_bf2(W2[n1 * 128 + kb + 8], W2[n1 * 128 + kb + 9]));
    }
    for (int idx = tid; idx < 8 * 32; idx += kThreads) {    // W1 k8 frag pairs
        int np = idx >> 5, ln = idx & 31;
        int n0 = (2 * np) * 8 + (ln >> 2);
        int n1 = n0 + 8;
        int kb = (ln & 3) * 2;
        ((uint2*)(sm + OFF_W1))[idx] = make_uint2(
            pack_bf2(W1[kb * 128 + n0], W1[(kb + 1) * 128 + n0]),
            pack_bf2(W1[kb * 128 + n1], W1[(kb + 1) * 128 + n1]));
    }
    for (int idx = tid; idx < 8 * 32; idx += kThreads) {    // W1^T: B(k,n) = W1[n*128+k]
        int ks = idx >> 5, ln = idx & 31;
        int n  = ln >> 2;
        int kb = ks * 16 + (ln & 3) * 2;
        ((uint2*)(sm + OFF_W1T))[idx] = make_uint2(
            pack_bf2(W1[n * 128 + kb],     W1[n * 128 + kb + 1]),
            pack_bf2(W1[n * 128 + kb + 8], W1[n * 128 + kb + 9]));
    }
    ((float*)(sm + OFF_B1))[tid] = b1[tid];
    ((float*)(sm + OFF_B2))[tid] = b2[tid];
    if (tid < 64) {
        sm[OFF_W3B  + tid] = pack_bf2( W3[2 * tid],  W3[2 * tid + 1]);
        sm[OFF_NW3B + tid] = pack_bf2(-W3[2 * tid], -W3[2 * tid + 1]);
    }
    __syncthreads();

    const uint4*    w2f  = (const uint4*)(sm + OFF_W2);
    const uint4*    w2tf = (const uint4*)(sm + OFF_W2T);
    const uint2*    w1f  = (const uint2*)(sm + OFF_W1);
    const uint2*    w1tf = (const uint2*)(sm + OFF_W1T);
    const float2*   b1v  = (const float2*)(sm + OFF_B1);
    const float2*   b2v  = (const float2*)(sm + OFF_B2);
    const uint32_t* w3b  = (const uint32_t*)(sm + OFF_W3B);
    const uint32_t* nw3b = (const uint32_t*)(sm + OFF_NW3B);
    (void)b3;  // constant offset: no effect on gradient

    const int gp = lane >> 2, tg = lane & 3;

    for (int t = blockIdx.x; t < kNumTiles; t += gridDim.x) {
        const int row0 = t * kRowsCTA + wid * 16;
        const float* zp = z + (size_t)(row0 + gp) * 8 + tg * 2;
        float s[4];
        {
            float2 v0 = *(const float2*)zp;          // row g
            float2 v1 = *(const float2*)(zp + 64);   // row g+8
            s[0] = v0.x; s[1] = v0.y; s[2] = v1.x; s[3] = v1.y;
        }
        float d[4], dsw[4];
#pragma unroll 1
        for (int it = 0; it < 4; it++) {
            grad_eval(w2f, w2tf, w1f, w1tf, b1v, b2v, w3b, nw3b, lane, s, d);
#pragma unroll
            for (int i = 0; i < 4; i++) dsw[i] = __shfl_xor_sync(0xffffffffu, d[i], 2);
            if ((it & 1) == 0) {
                if (tg < 2) {               // q cols: q += dt * dHdp
#pragma unroll
                    for (int i = 0; i < 4; i++) s[i] += kDT * dsw[i];
                } else {                    // p cols: p -= dt/2 * dHdq
#pragma unroll
                    for (int i = 0; i < 4; i++) s[i] -= 0.5f * kDT * dsw[i];
                }
            } else {
                if (tg >= 2) {              // p cols: p = p_half - dt/2 * dHdq_new
#pragma unroll
                    for (int i = 0; i < 4; i++) s[i] -= 0.5f * kDT * dsw[i];
                }
            }
        }
        float* op = out + (size_t)(row0 + gp) * 8 + tg * 2;
        *(float2*)op        = make_float2(s[0], s[1]);
        *(float2*)(op + 64) = make_float2(s[2], s[3]);
    }
}

extern "C" void kernel_launch(void* const* d_in, const int* in_sizes, int n_in,
                              void* d_out, int out_size) {
    const float* z  = (const float*)d_in[0];
    const float* W1 = (const float*)d_in[1];
    const float* b1 = (const float*)d_in[2];
    const float* W2 = (const float*)d_in[3];
    const float* b2 = (const float*)d_in[4];
    const float* W3 = (const float*)d_in[5];
    const float* b3 = (const float*)d_in[6];
    constexpr int kSmemBytes = kSmemU32 * 4;
    cudaFuncSetAttribute(symp_kernel, cudaFuncAttributeMaxDynamicSharedMemorySize, kSmemBytes);
    int grid = 444;                       // 3 persistent CTAs / SM x 148 SMs
    if (grid > kNumTiles) grid = kNumTiles;
    symp_kernel<<<grid, kThreads, kSmemBytes>>>(z, W1, b1, W2, b2, W3, b3, (float*)d_out);
    (void)in_sizes; (void)n_in; (void)out_size;
}